// round 15
// baseline (speedup 1.0000x reference)
#include <cuda_runtime.h>
#include <cuda_bf16.h>
#include <math.h>

#define BB 16
#define CC 256
#define TT 4096
#define KK 5

#define TTILE 256
#define WIN   294   // window: x[t0-16 .. t0+277]
#define WOFF  16

// ===========================================================================
// Precomputed B fragments (bf16 hi/lo, packed pairs) for mma.m16n8k16.row.col.
// (identical to round 14)
// ===========================================================================
__device__ __align__(16) unsigned g_wfrag[2 * 48 * 2 * 8 * 32 * 2];

__device__ __forceinline__ unsigned short bf16bits(float v) {
    return (unsigned short)(__bfloat16_as_ushort(__float2bfloat16_rn(v)));
}

__global__ void prep_wfrag(const float* __restrict__ rp1_w) {
    int e = blockIdx.x * blockDim.x + threadIdx.x;
    if (e >= 2 * 48 * 2 * 8 * 32 * 2) return;
    int r2   = e & 1;
    int lane = (e >> 1) & 31;
    int nt   = (e >> 6) & 7;
    int wn   = (e >> 9) & 1;
    int kc   = (e >> 10) % 48;
    int p    = (e >> 10) / 48;
    int tig = lane & 3;
    int g   = lane >> 2;
    int n = wn * 64 + nt * 8 + g;
    int k = kc * 16 + 2 * tig + r2 * 8;
    unsigned out = 0;
    #pragma unroll
    for (int q = 0; q < 2; q++) {
        int kk = k + q;
        int c = kk / 3, d = kk - 3 * c;
        float w = __ldg(rp1_w + (n * CC + c) * 3 + d);
        float hi = __bfloat162float(__float2bfloat16_rn(w));
        float val = p ? (w - hi) : hi;
        out |= ((unsigned)bf16bits(val)) << (16 * q);
    }
    g_wfrag[e] = out;
}

__device__ __forceinline__ void mma16(float* d, const unsigned* a, unsigned b0, unsigned b1) {
    asm volatile(
        "mma.sync.aligned.m16n8k16.row.col.f32.bf16.bf16.f32 "
        "{%0,%1,%2,%3},{%4,%5,%6,%7},{%8,%9},{%0,%1,%2,%3};"
        : "+f"(d[0]), "+f"(d[1]), "+f"(d[2]), "+f"(d[3])
        : "r"(a[0]), "r"(a[1]), "r"(a[2]), "r"(a[3]), "r"(b0), "r"(b1));
}

__device__ __forceinline__ unsigned packbf2(float lo_elem, float hi_elem) {
    unsigned r;
    asm("cvt.rn.bf16x2.f32 %0, %1, %2;" : "=r"(r) : "f"(hi_elem), "f"(lo_elem));
    return r;
}

// ===========================================================================
// Kernel 1: k_deform, 256-thread CTAs (256-t tiles) + float4 weight loads.
// All computed values and fma orders bit-identical to rounds 5-14.
// smem: s_w 256*32 | s_dw 256*5 | s_b 32*WIN = 18880 floats (75.5 KB).
// ===========================================================================
#define DEF_SMEM_FLOATS (CC * 32 + CC * KK + 32 * WIN)

__global__ __launch_bounds__(256) void k_deform(
    const float* __restrict__ x,
    const float* __restrict__ ow, const float* __restrict__ ob,
    const float* __restrict__ mw, const float* __restrict__ mb,
    const float* __restrict__ weight,
    float* __restrict__ deformed)
{
    extern __shared__ float dsm_d[];
    float* s_w  = dsm_d;                    // [c][32]: 0..14 offset, 15..29 mod, 30..31 pad
    float* s_dw = dsm_d + CC * 32;          // [c][5] diag weights
    float* s_b  = dsm_d + CC * 32 + CC * KK;

    const int tid = threadIdx.x;
    const int t0 = blockIdx.x * TTILE;
    const int b = blockIdx.y;
    const float* xb = x + (size_t)b * CC * TT;

    for (int i = tid; i < CC * 32; i += TTILE) {
        int c = i >> 5;
        int j = i & 31;
        float v = 0.f;
        if (j < 15) {
            int k = j / 3, d = j - k * 3;
            v = ow[k * (CC * 3) + c * 3 + d];
        } else if (j < 30) {
            int jj = j - 15;
            int k = jj / 3, d = jj - k * 3;
            v = mw[k * (CC * 3) + c * 3 + d];
        }
        s_w[i] = v;
    }

    float offa[KK] = {0.f, 0.f, 0.f, 0.f, 0.f};
    float moda[KK] = {0.f, 0.f, 0.f, 0.f, 0.f};

    // Phase A: 10-channel conv (chunk-folded fp32 accumulation — frozen order)
    for (int cc = 0; cc < CC; cc += 32) {
        __syncthreads();
        for (int idx = tid; idx < 32 * WIN; idx += TTILE) {
            int ci = idx / WIN;
            int u = idx - ci * WIN;
            int tg = t0 - WOFF + u;
            s_b[idx] = (tg >= 0 && tg < TT) ? __ldg(xb + (size_t)(cc + ci) * TT + tg) : 0.f;
        }
        __syncthreads();
        float offc[KK] = {0.f, 0.f, 0.f, 0.f, 0.f};
        float modc[KK] = {0.f, 0.f, 0.f, 0.f, 0.f};
        #pragma unroll 1
        for (int ci = 0; ci < 32; ci++) {
            const float4* w4 = reinterpret_cast<const float4*>(s_w + (cc + ci) * 32);
            const float* xs = s_b + ci * WIN + tid + (WOFF - 1);
            float x0 = xs[0];
            float x1 = xs[1];
            float x2 = xs[2];
            // sliding two-float4 window; each weight used once, order frozen
            float4 va = w4[0];                       // w0..w3
            float4 vb = w4[1];                       // w4..w7
            offc[0] += x0 * va.x + x1 * va.y + x2 * va.z;
            offc[1] += x0 * va.w + x1 * vb.x + x2 * vb.y;
            va = w4[2];                              // w8..w11
            offc[2] += x0 * vb.z + x1 * vb.w + x2 * va.x;
            offc[3] += x0 * va.y + x1 * va.z + x2 * va.w;
            vb = w4[3];                              // w12..w15
            offc[4] += x0 * vb.x + x1 * vb.y + x2 * vb.z;
            va = w4[4];                              // w16..w19
            modc[0] += x0 * vb.w + x1 * va.x + x2 * va.y;
            vb = w4[5];                              // w20..w23
            modc[1] += x0 * va.z + x1 * va.w + x2 * vb.x;
            modc[2] += x0 * vb.y + x1 * vb.z + x2 * vb.w;
            va = w4[6];                              // w24..w27
            modc[3] += x0 * va.x + x1 * va.y + x2 * va.z;
            vb = w4[7];                              // w28..w31
            modc[4] += x0 * va.w + x1 * vb.x + x2 * vb.y;
        }
        #pragma unroll
        for (int k = 0; k < KK; k++) { offa[k] += offc[k]; moda[k] += modc[k]; }
    }

    // positions / interp weights (exact fp32 — frozen)
    const int t = t0 + tid;
    float mf[KK], mc[KK];
    int pfi[KK], pci[KK];
    #pragma unroll
    for (int k = 0; k < KK; k++) {
        float off = offa[k] + __ldg(ob + k);
        float z = moda[k] + __ldg(mb + k);
        float mod = 1.f / (1.f + expf(-z));
        float pos = (float)(t + k - 2) + off;
        pos = fminf(fmaxf(pos, 0.f), (float)(TT - 1));
        float pf = floorf(pos);
        float pc = ceilf(pos);
        mf[k] = (pc - pos) * mod;
        mc[k] = (pos - pf) * mod;
        pfi[k] = (int)pf;
        pci[k] = (int)pc;
    }

    int idxf[KK], idxc[KK];
    bool allin = true;
    #pragma unroll
    for (int k = 0; k < KK; k++) {
        idxf[k] = pfi[k] - (t0 - WOFF);
        idxc[k] = pci[k] - (t0 - WOFF);
        allin = allin && ((unsigned)idxf[k] < (unsigned)WIN) && ((unsigned)idxc[k] < (unsigned)WIN);
    }
    const bool fast = __all_sync(0xffffffffu, allin);

    __syncthreads();
    for (int i = tid; i < CC * KK; i += TTILE) {
        int c = i / KK;
        int k = i - c * KK;
        s_dw[i] = __ldg(weight + ((size_t)c * CC + c) * KK + k);
    }

    // Phase B: sample + diag einsum (unchanged logic)
    float* db = deformed + (size_t)b * CC * TT;
    for (int cc = 0; cc < CC; cc += 32) {
        __syncthreads();
        for (int idx = tid; idx < 32 * WIN; idx += TTILE) {
            int ci = idx / WIN;
            int u = idx - ci * WIN;
            int tg = t0 - WOFF + u;
            s_b[idx] = (tg >= 0 && tg < TT) ? __ldg(xb + (size_t)(cc + ci) * TT + tg) : 0.f;
        }
        __syncthreads();
        if (fast) {
            #pragma unroll 2
            for (int ci = 0; ci < 32; ci++) {
                const float* xs = s_b + ci * WIN;
                const float* dwc = s_dw + (cc + ci) * KK;
                float acc = 0.f;
                #pragma unroll
                for (int k = 0; k < KK; k++) {
                    float s = xs[idxf[k]] * mf[k] + xs[idxc[k]] * mc[k];
                    acc = fmaf(s, dwc[k], acc);
                }
                db[(size_t)(cc + ci) * TT + t] = acc;
            }
        } else {
            #pragma unroll 1
            for (int ci = 0; ci < 32; ci++) {
                const float* xc = xb + (size_t)(cc + ci) * TT;
                const float* dwc = s_dw + (cc + ci) * KK;
                float acc = 0.f;
                #pragma unroll
                for (int k = 0; k < KK; k++) {
                    float s = __ldg(xc + pfi[k]) * mf[k] + __ldg(xc + pci[k]) * mc[k];
                    acc = fmaf(s, dwc[k], acc);
                }
                db[(size_t)(cc + ci) * TT + t] = acc;
            }
        }
    }
}

// ===========================================================================
// Kernel 2: round-14 k_recover2 VERBATIM (bf16 3-split m16n8k16, ~157us)
// ===========================================================================
#define REC_SMEM_FLOATS (2 * 64 * 132)

__global__ __launch_bounds__(256, 2) void k_recover2(
    const float* __restrict__ deformed,
    const float* __restrict__ rp1_b,
    const float* __restrict__ rp2_w,
    const float* __restrict__ rp2_b,
    float* __restrict__ recovery)
{
    extern __shared__ float dsm_r[];
    float* shi = dsm_r;
    float* slo = dsm_r + 64 * 132;
    __shared__ float sp[2][128];

    const int tid = threadIdx.x;
    const int wid = tid >> 5;
    const int lane = tid & 31;
    const int wm = wid & 3;
    const int wn = wid >> 2;
    const int tig = lane & 3;
    const int g = lane >> 2;

    const int bx = blockIdx.x;
    const int b  = bx >> 5;
    const int t0 = (bx & 31) << 7;
    const float* db = deformed + (size_t)b * CC * TT;
    const uint2* Wf2 = reinterpret_cast<const uint2*>(g_wfrag);

    float dacc[2][8][4];
    #pragma unroll
    for (int mt = 0; mt < 2; mt++)
        #pragma unroll
        for (int nt = 0; nt < 8; nt++)
            #pragma unroll
            for (int r = 0; r < 4; r++) dacc[mt][nt][r] = 0.f;

    const int ttb = wm * 32 + g;

    for (int cg = 0; cg < 4; cg++) {
        __syncthreads();
        for (int i = tid; i < 64 * 130; i += 256) {
            int j = i / 130;
            int u = i - j * 130;
            int tg = t0 - 1 + u;
            float v = (tg >= 0 && tg < TT)
                ? __ldg(db + (size_t)(cg * 64 + j) * TT + tg) : 0.f;
            float hi = __bfloat162float(__float2bfloat16_rn(v));
            shi[j * 132 + u] = hi;
            slo[j * 132 + u] = __bfloat162float(__float2bfloat16_rn(v - hi));
        }
        __syncthreads();

        #pragma unroll 2
        for (int kcl = 0; kcl < 12; kcl++) {
            const int kc = cg * 12 + kcl;
            const int kb = kc * 16;
            const int k0 = kb + 2 * tig;
            const int c0 = k0 / 3,        d0 = k0 - 3 * c0;
            const int c1 = (k0 + 1) / 3,  d1 = (k0 + 1) - 3 * c1;
            const int c2k = (k0 + 8) / 3, d2 = (k0 + 8) - 3 * c2k;
            const int c3 = (k0 + 9) / 3,  d3 = (k0 + 9) - 3 * c3;
            const int o0 = (c0 - cg * 64) * 132 + d0;
            const int o1 = (c1 - cg * 64) * 132 + d1;
            const int o2 = (c2k - cg * 64) * 132 + d2;
            const int o3 = (c3 - cg * 64) * 132 + d3;

            unsigned ahi[2][4], alo[2][4];
            #pragma unroll
            for (int mt = 0; mt < 2; mt++) {
                const int tt = ttb + mt * 16;
                ahi[mt][0] = packbf2(shi[o0 + tt],     shi[o1 + tt]);
                ahi[mt][1] = packbf2(shi[o0 + tt + 8], shi[o1 + tt + 8]);
                ahi[mt][2] = packbf2(shi[o2 + tt],     shi[o3 + tt]);
                ahi[mt][3] = packbf2(shi[o2 + tt + 8], shi[o3 + tt + 8]);
                alo[mt][0] = packbf2(slo[o0 + tt],     slo[o1 + tt]);
                alo[mt][1] = packbf2(slo[o0 + tt + 8], slo[o1 + tt + 8]);
                alo[mt][2] = packbf2(slo[o2 + tt],     slo[o3 + tt]);
                alo[mt][3] = packbf2(slo[o2 + tt + 8], slo[o3 + tt + 8]);
            }

            const int fb = ((kc * 2 + wn) * 8) * 32 + lane;
            const int fl = (((48 + kc) * 2 + wn) * 8) * 32 + lane;
            #pragma unroll
            for (int nt = 0; nt < 8; nt++) {
                uint2 bh = __ldg(Wf2 + fb + nt * 32);
                uint2 bl = __ldg(Wf2 + fl + nt * 32);
                #pragma unroll
                for (int mt = 0; mt < 2; mt++) {
                    mma16(dacc[mt][nt], ahi[mt], bh.x, bh.y);
                    mma16(dacc[mt][nt], ahi[mt], bl.x, bl.y);
                    mma16(dacc[mt][nt], alo[mt], bh.x, bh.y);
                }
            }
        }
    }

    #pragma unroll
    for (int mt = 0; mt < 2; mt++) {
        float s0 = 0.f, s8 = 0.f;
        #pragma unroll
        for (int nt = 0; nt < 8; nt++) {
            int c2 = wn * 64 + nt * 8 + tig * 2;
            float b1a = __ldg(rp1_b + c2),     b1b = __ldg(rp1_b + c2 + 1);
            float w2a = __ldg(rp2_w + c2),     w2b = __ldg(rp2_w + c2 + 1);
            s0 += fmaxf(dacc[mt][nt][0] + b1a, 0.f) * w2a
                + fmaxf(dacc[mt][nt][1] + b1b, 0.f) * w2b;
            s8 += fmaxf(dacc[mt][nt][2] + b1a, 0.f) * w2a
                + fmaxf(dacc[mt][nt][3] + b1b, 0.f) * w2b;
        }
        s0 += __shfl_xor_sync(0xffffffffu, s0, 1);
        s0 += __shfl_xor_sync(0xffffffffu, s0, 2);
        s8 += __shfl_xor_sync(0xffffffffu, s8, 1);
        s8 += __shfl_xor_sync(0xffffffffu, s8, 2);
        if (tig == 0) {
            sp[wn][wm * 32 + mt * 16 + g] = s0;
            sp[wn][wm * 32 + mt * 16 + g + 8] = s8;
        }
    }
    __syncthreads();

    if (tid < 128) {
        recovery[(size_t)b * TT + t0 + tid] = sp[0][tid] + sp[1][tid] + __ldg(rp2_b);
    }
}

// ---------------------------------------------------------------------------
extern "C" void kernel_launch(void* const* d_in, const int* in_sizes, int n_in,
                              void* d_out, int out_size) {
    const float* x     = (const float*)d_in[0];
    const float* ow    = (const float*)d_in[1];
    const float* ob    = (const float*)d_in[2];
    const float* mw    = (const float*)d_in[3];
    const float* mb    = (const float*)d_in[4];
    const float* wgt   = (const float*)d_in[5];
    const float* rp1_w = (const float*)d_in[6];
    const float* rp1_b = (const float*)d_in[7];
    const float* rp2_w = (const float*)d_in[8];
    const float* rp2_b = (const float*)d_in[9];

    float* out = (float*)d_out;
    float* deformed = out;                              // (B, C, T)
    float* recovery = out + (size_t)BB * CC * TT;       // (B, T)

    cudaFuncSetAttribute(k_deform, cudaFuncAttributeMaxDynamicSharedMemorySize,
                         DEF_SMEM_FLOATS * (int)sizeof(float));
    cudaFuncSetAttribute(k_recover2, cudaFuncAttributeMaxDynamicSharedMemorySize,
                         REC_SMEM_FLOATS * (int)sizeof(float));

    prep_wfrag<<<(2 * 48 * 2 * 8 * 32 * 2 + 255) / 256, 256>>>(rp1_w);
    k_deform<<<dim3(TT / TTILE, BB), TTILE, DEF_SMEM_FLOATS * sizeof(float)>>>(
        x, ow, ob, mw, mb, wgt, deformed);
    k_recover2<<<512, 256, REC_SMEM_FLOATS * sizeof(float)>>>(
        deformed, rp1_b, rp2_w, rp2_b, recovery);
}